// round 1
// baseline (speedup 1.0000x reference)
#include <cuda_runtime.h>
#include <cstdint>

// Problem constants
#define BB   16
#define HH   64
#define WW   64
#define CC   768
#define NHD  12
#define KDIM 64
#define GRP  6            // heads per axis group
#define MTOT (BB*HH*WW)   // 65536
#define INV_SCALE 0.125f  // 1/sqrt(64)

// Scratch (static device allocation — allowed)
__device__ float g_q[MTOT * CC];
__device__ float g_k[MTOT * CC];
__device__ float g_v[MTOT * CC];
__device__ float g_attn[MTOT * CC];

// ---------------------------------------------------------------------------
// Tiled fp32 SGEMM: C[M,N] = A[M,K] * B[K,N] + bias[N]
// BM=BN=128, BK=8, 256 threads, 8x8 microtile. M,N multiples of 128, K of 8.
// ---------------------------------------------------------------------------
__global__ void __launch_bounds__(256, 2) sgemm_bias_kernel(
    const float* __restrict__ A, const float* __restrict__ B,
    const float* __restrict__ bias, float* __restrict__ C,
    int M, int N, int K)
{
    __shared__ float As[8][128];
    __shared__ float Bs[8][128];

    const int bn  = blockIdx.x;       // N tile
    const int bm  = blockIdx.y;       // M tile
    const int tid = threadIdx.x;

    const int arow = tid >> 1;          // 0..127
    const int acol = (tid & 1) * 4;     // 0 or 4
    const int brow = tid >> 5;          // 0..7
    const int bcol = (tid & 31) * 4;    // 0..124

    const float* Ab = A + (size_t)(bm * 128) * K;
    const float* Bb = B + bn * 128;

    const int tx = tid & 15;
    const int ty = tid >> 4;

    float acc[8][8];
    #pragma unroll
    for (int i = 0; i < 8; i++)
        #pragma unroll
        for (int j = 0; j < 8; j++) acc[i][j] = 0.0f;

    for (int k0 = 0; k0 < K; k0 += 8) {
        float4 a4 = *(const float4*)(Ab + (size_t)arow * K + k0 + acol);
        As[acol + 0][arow] = a4.x;
        As[acol + 1][arow] = a4.y;
        As[acol + 2][arow] = a4.z;
        As[acol + 3][arow] = a4.w;
        float4 b4 = *(const float4*)(Bb + (size_t)(k0 + brow) * N + bcol);
        *(float4*)&Bs[brow][bcol] = b4;
        __syncthreads();

        #pragma unroll
        for (int k = 0; k < 8; k++) {
            float4 a0 = *(const float4*)&As[k][ty * 8];
            float4 a1 = *(const float4*)&As[k][ty * 8 + 4];
            float4 b0 = *(const float4*)&Bs[k][tx * 8];
            float4 b1 = *(const float4*)&Bs[k][tx * 8 + 4];
            float ar[8] = {a0.x, a0.y, a0.z, a0.w, a1.x, a1.y, a1.z, a1.w};
            float br[8] = {b0.x, b0.y, b0.z, b0.w, b1.x, b1.y, b1.z, b1.w};
            #pragma unroll
            for (int i = 0; i < 8; i++)
                #pragma unroll
                for (int j = 0; j < 8; j++)
                    acc[i][j] = fmaf(ar[i], br[j], acc[i][j]);
        }
        __syncthreads();
    }

    // epilogue
    #pragma unroll
    for (int i = 0; i < 8; i++) {
        int row = bm * 128 + ty * 8 + i;
        #pragma unroll
        for (int j = 0; j < 8; j += 4) {
            int col = bn * 128 + tx * 8 + j;
            float4 o;
            o.x = acc[i][j + 0] + bias[col + 0];
            o.y = acc[i][j + 1] + bias[col + 1];
            o.z = acc[i][j + 2] + bias[col + 2];
            o.w = acc[i][j + 3] + bias[col + 3];
            *(float4*)(C + (size_t)row * N + col) = o;
        }
    }
}

// ---------------------------------------------------------------------------
// Axial attention: one CTA per (axis, b, fixed, head). seq=64, d=64.
// smem: Qs[64][64], Ks[64][65], Vs[64][64], Ss[64][65]  (66048 B dynamic)
// ---------------------------------------------------------------------------
__global__ void __launch_bounds__(256) attn_kernel()
{
    extern __shared__ float smem[];
    float* Qs = smem;                 // [64][64]
    float* Ks = Qs + 64 * 64;         // [64][65] padded
    float* Vs = Ks + 64 * 65;         // [64][64]
    float* Ss = Vs + 64 * 64;         // [64][65] padded

    const int tid = threadIdx.x;
    int idx = blockIdx.x;
    const int axis = idx / (BB * WW * GRP);   // 0: attend along H, 1: along W
    idx -= axis * (BB * WW * GRP);
    const int b     = idx / (WW * GRP);
    int rem         = idx - b * (WW * GRP);
    const int fixed = rem / GRP;              // w for axis0, h for axis1
    const int n     = rem - fixed * GRP;      // head within group

    size_t base;
    int stride;
    if (axis == 0) {
        // seq index = h; fixed w; heads 0..5
        base   = ((size_t)b * HH * WW + fixed) * CC + n * KDIM;
        stride = WW * CC;
    } else {
        // seq index = w; fixed h; heads 6..11
        base   = ((size_t)(b * HH + fixed)) * (size_t)(WW * CC) + (n + GRP) * KDIM;
        stride = CC;
    }

    // Load Q, K, V tiles (coalesced 64-float rows)
    for (int t = tid; t < 64 * 64; t += 256) {
        int i = t >> 6, d = t & 63;
        size_t off = base + (size_t)i * stride + d;
        Qs[i * 64 + d] = g_q[off];
        Ks[i * 65 + d] = g_k[off];
        Vs[i * 64 + d] = g_v[off];
    }
    __syncthreads();

    const int tx = tid & 15;   // 0..15
    const int ty = tid >> 4;   // 0..15
    const int i0 = ty * 4;
    const int j0 = tx * 4;

    // S = (Q K^T) / 8
    {
        float acc[4][4];
        #pragma unroll
        for (int a = 0; a < 4; a++)
            #pragma unroll
            for (int c = 0; c < 4; c++) acc[a][c] = 0.0f;
        #pragma unroll 4
        for (int d = 0; d < 64; d++) {
            float qr[4], kr[4];
            #pragma unroll
            for (int a = 0; a < 4; a++) qr[a] = Qs[(i0 + a) * 64 + d];
            #pragma unroll
            for (int c = 0; c < 4; c++) kr[c] = Ks[(j0 + c) * 65 + d];
            #pragma unroll
            for (int a = 0; a < 4; a++)
                #pragma unroll
                for (int c = 0; c < 4; c++)
                    acc[a][c] = fmaf(qr[a], kr[c], acc[a][c]);
        }
        #pragma unroll
        for (int a = 0; a < 4; a++)
            #pragma unroll
            for (int c = 0; c < 4; c++)
                Ss[(i0 + a) * 65 + (j0 + c)] = acc[a][c] * INV_SCALE;
    }
    __syncthreads();

    // Row softmax: warp handles 8 rows, lane covers j = lane, lane+32
    {
        const int lane = tid & 31;
        const int warp = tid >> 5;
        for (int r = warp * 8; r < warp * 8 + 8; r++) {
            float x0 = Ss[r * 65 + lane];
            float x1 = Ss[r * 65 + lane + 32];
            float m = fmaxf(x0, x1);
            #pragma unroll
            for (int o = 16; o > 0; o >>= 1)
                m = fmaxf(m, __shfl_xor_sync(0xffffffffu, m, o));
            float e0 = __expf(x0 - m);
            float e1 = __expf(x1 - m);
            float s = e0 + e1;
            #pragma unroll
            for (int o = 16; o > 0; o >>= 1)
                s += __shfl_xor_sync(0xffffffffu, s, o);
            float inv = 1.0f / s;
            Ss[r * 65 + lane]      = e0 * inv;
            Ss[r * 65 + lane + 32] = e1 * inv;
        }
    }
    __syncthreads();

    // O = P V ; thread computes rows i0..i0+3, cols j0..j0+3 (d dimension)
    {
        float acc[4][4];
        #pragma unroll
        for (int a = 0; a < 4; a++)
            #pragma unroll
            for (int c = 0; c < 4; c++) acc[a][c] = 0.0f;
        #pragma unroll 4
        for (int j = 0; j < 64; j++) {
            float pr[4], vr[4];
            #pragma unroll
            for (int a = 0; a < 4; a++) pr[a] = Ss[(i0 + a) * 65 + j];
            #pragma unroll
            for (int c = 0; c < 4; c++) vr[c] = Vs[j * 64 + j0 + c];
            #pragma unroll
            for (int a = 0; a < 4; a++)
                #pragma unroll
                for (int c = 0; c < 4; c++)
                    acc[a][c] = fmaf(pr[a], vr[c], acc[a][c]);
        }
        #pragma unroll
        for (int a = 0; a < 4; a++) {
            size_t off = base + (size_t)(i0 + a) * stride + j0;
            float4 o = make_float4(acc[a][0], acc[a][1], acc[a][2], acc[a][3]);
            *(float4*)(g_attn + off) = o;
        }
    }
}

// ---------------------------------------------------------------------------
extern "C" void kernel_launch(void* const* d_in, const int* in_sizes, int n_in,
                              void* d_out, int out_size)
{
    const float* queries = (const float*)d_in[0];
    const float* values  = (const float*)d_in[1];
    const float* Wq = (const float*)d_in[2];
    const float* bq = (const float*)d_in[3];
    const float* Wk = (const float*)d_in[4];
    const float* bk = (const float*)d_in[5];
    const float* Wv = (const float*)d_in[6];
    const float* bv = (const float*)d_in[7];
    const float* Wo = (const float*)d_in[8];
    const float* bo = (const float*)d_in[9];
    float* out = (float*)d_out;

    float *qp, *kp, *vp, *ap;
    cudaGetSymbolAddress((void**)&qp, g_q);
    cudaGetSymbolAddress((void**)&kp, g_k);
    cudaGetSymbolAddress((void**)&vp, g_v);
    cudaGetSymbolAddress((void**)&ap, g_attn);

    const int smem_attn = (64 * 64 + 64 * 65 + 64 * 64 + 64 * 65) * 4; // 66048
    cudaFuncSetAttribute(attn_kernel, cudaFuncAttributeMaxDynamicSharedMemorySize,
                         smem_attn);

    dim3 ggrid(CC / 128, MTOT / 128);   // (6, 512)
    // QKV projections
    sgemm_bias_kernel<<<ggrid, 256>>>(queries, Wq, bq, qp, MTOT, CC, CC);
    sgemm_bias_kernel<<<ggrid, 256>>>(values,  Wk, bk, kp, MTOT, CC, CC);
    sgemm_bias_kernel<<<ggrid, 256>>>(values,  Wv, bv, vp, MTOT, CC, CC);
    // Axial attention (both axes, all heads)
    attn_kernel<<<2 * BB * WW * GRP, 256, smem_attn>>>();
    // Output projection
    sgemm_bias_kernel<<<ggrid, 256>>>(ap, Wo, bo, out, MTOT, CC, CC);
}

// round 4
// speedup vs baseline: 2.2207x; 2.2207x over previous
#include <cuda_runtime.h>
#include <cuda_bf16.h>
#include <cstdint>

// Problem constants
#define BB   16
#define HH   64
#define WW   64
#define CC   768
#define GRP  6            // heads per axis group
#define MTOT (BB*HH*WW)   // 65536
#define INV_SCALE 0.125f  // 1/sqrt(64)

// ---------------------------------------------------------------------------
// Static device scratch
// ---------------------------------------------------------------------------
__device__ float g_q[MTOT * CC];
__device__ float g_k[MTOT * CC];
__device__ float g_v[MTOT * CC];
__device__ __nv_bfloat16 g_qh[MTOT * CC];
__device__ __nv_bfloat16 g_ql[MTOT * CC];
__device__ __nv_bfloat16 g_vh[MTOT * CC];
__device__ __nv_bfloat16 g_vl[MTOT * CC];
__device__ __nv_bfloat16 g_ah[MTOT * CC];
__device__ __nv_bfloat16 g_al[MTOT * CC];
// transposed split weights: [4][N=768][K=768], order q,k,v,o
__device__ __nv_bfloat16 g_wth[4][CC * CC];
__device__ __nv_bfloat16 g_wtl[4][CC * CC];

// ---------------------------------------------------------------------------
// helpers
// ---------------------------------------------------------------------------
__device__ __forceinline__ uint32_t smem_u32(const void* p) {
    uint32_t a;
    asm("{ .reg .u64 t; cvta.to.shared.u64 t, %1; cvt.u32.u64 %0, t; }"
        : "=r"(a) : "l"(p));
    return a;
}
__device__ __forceinline__ uint32_t packbf(__nv_bfloat16 a, __nv_bfloat16 b) {
    return (uint32_t)__bfloat16_as_ushort(a) |
           ((uint32_t)__bfloat16_as_ushort(b) << 16);
}
__device__ __forceinline__ void cp16(uint32_t dst, const void* src) {
    asm volatile("cp.async.cg.shared.global [%0], [%1], 16;"
                 :: "r"(dst), "l"(src) : "memory");
}
__device__ __forceinline__ void ldsm4(uint32_t* r, uint32_t addr) {
    asm volatile("ldmatrix.sync.aligned.m8n8.x4.shared.b16 {%0,%1,%2,%3}, [%4];"
                 : "=r"(r[0]), "=r"(r[1]), "=r"(r[2]), "=r"(r[3]) : "r"(addr));
}
__device__ __forceinline__ void mma16816(float* d, const uint32_t* a,
                                         const uint32_t* b) {
    asm volatile(
        "mma.sync.aligned.m16n8k16.row.col.f32.bf16.bf16.f32 "
        "{%0,%1,%2,%3}, {%4,%5,%6,%7}, {%8,%9}, {%0,%1,%2,%3};"
        : "+f"(d[0]), "+f"(d[1]), "+f"(d[2]), "+f"(d[3])
        : "r"(a[0]), "r"(a[1]), "r"(a[2]), "r"(a[3]), "r"(b[0]), "r"(b[1]));
}

// ---------------------------------------------------------------------------
// Split conversion: fp32 -> bf16 hi + bf16 lo (4 elems / thread)
// ---------------------------------------------------------------------------
__global__ void conv_split(const float4* __restrict__ x, uint2* __restrict__ h,
                           uint2* __restrict__ l, int n4) {
    int i = blockIdx.x * blockDim.x + threadIdx.x;
    if (i >= n4) return;
    float4 v = x[i];
    __nv_bfloat16 h0 = __float2bfloat16(v.x), h1 = __float2bfloat16(v.y);
    __nv_bfloat16 h2 = __float2bfloat16(v.z), h3 = __float2bfloat16(v.w);
    __nv_bfloat16 l0 = __float2bfloat16(v.x - __bfloat162float(h0));
    __nv_bfloat16 l1 = __float2bfloat16(v.y - __bfloat162float(h1));
    __nv_bfloat16 l2 = __float2bfloat16(v.z - __bfloat162float(h2));
    __nv_bfloat16 l3 = __float2bfloat16(v.w - __bfloat162float(h3));
    h[i] = make_uint2(packbf(h0, h1), packbf(h2, h3));
    l[i] = make_uint2(packbf(l0, l1), packbf(l2, l3));
}

// ---------------------------------------------------------------------------
// Weight transpose + split: W[K=768][N=768] -> Th/Tl [N=768][K=768] bf16
// ---------------------------------------------------------------------------
__global__ void wt_split(const float* __restrict__ W, __nv_bfloat16* __restrict__ Th,
                         __nv_bfloat16* __restrict__ Tl) {
    __shared__ float t[32][33];
    int nb = blockIdx.x * 32, kb = blockIdx.y * 32;
    int tx = threadIdx.x, ty = threadIdx.y;
    #pragma unroll
    for (int j = 0; j < 32; j += 8)
        t[ty + j][tx] = W[(size_t)(kb + ty + j) * CC + nb + tx];
    __syncthreads();
    #pragma unroll
    for (int j = 0; j < 32; j += 8) {
        float v = t[tx][ty + j];   // = W[kb+tx][nb+ty+j]
        __nv_bfloat16 h = __float2bfloat16(v);
        __nv_bfloat16 l = __float2bfloat16(v - __bfloat162float(h));
        size_t o = (size_t)(nb + ty + j) * CC + kb + tx;
        Th[o] = h;
        Tl[o] = l;
    }
}

// ---------------------------------------------------------------------------
// mma.sync bf16 split GEMM: C[M,N] = (Ah+Al)[M,K]*(Bh+Bl)^T[N,K] + bias[N]
// CTA tile 128x128, BK=64 elems (128B rows), 3-stage cp.async.
// 256 threads (8 warps, 4Mx2N). rows padded to 144B -> ldmatrix conflict-free.
// ---------------------------------------------------------------------------
#define NS       3
#define ROWB     144                    // padded row stride in bytes (128 data)
#define TILEB    (128 * ROWB)           // 18432 B per tile
#define STAGEB   (4 * TILEB)            // Ah, Al, Bh, Bl = 73728 B
#define GEMM_SMEM (NS * STAGEB)         // 221184 B

__global__ void __launch_bounds__(256, 1) gemm_bf16s(
    const __nv_bfloat16* __restrict__ Ah, const __nv_bfloat16* __restrict__ Al,
    const __nv_bfloat16* __restrict__ Bh, const __nv_bfloat16* __restrict__ Bl,
    const float* __restrict__ bias, float* __restrict__ C)
{
    extern __shared__ char sm_raw[];
    const uint32_t s0 = smem_u32(sm_raw);

    const int tid  = threadIdx.x;
    const int lane = tid & 31;
    const int wid  = tid >> 5;
    const int wm   = wid >> 1;          // 0..3 -> M offset wm*32
    const int wn   = wid & 1;           // 0..1 -> N offset wn*64

    const int bn = blockIdx.x, bm = blockIdx.y;
    const size_t arow0 = (size_t)bm * 128;
    const size_t brow0 = (size_t)bn * 128;

    // producer mapping: pu = 16B unit within 128B row (0..7), pr = row (0..31)
    const int pu = tid & 7;
    const int pr = tid >> 3;

    float acc[2][8][4];
    #pragma unroll
    for (int mt = 0; mt < 2; mt++)
        #pragma unroll
        for (int nt = 0; nt < 8; nt++)
            #pragma unroll
            for (int e = 0; e < 4; e++) acc[mt][nt][e] = 0.0f;

    // --- prefetch first NS chunks ---
    #pragma unroll
    for (int c = 0; c < NS; c++) {
        const uint32_t stg = s0 + c * STAGEB;
        const int k0 = c * 64;
        #pragma unroll
        for (int p = 0; p < 4; p++) {
            int r = pr + p * 32;
            uint32_t d = stg + r * ROWB + pu * 16;
            size_t ga = (arow0 + r) * CC + k0 + pu * 8;
            size_t gb = (brow0 + r) * CC + k0 + pu * 8;
            cp16(d,              Ah + ga);
            cp16(d + TILEB,      Al + ga);
            cp16(d + 2 * TILEB,  Bh + gb);
            cp16(d + 3 * TILEB,  Bl + gb);
        }
        asm volatile("cp.async.commit_group;" ::: "memory");
    }

    for (int c = 0; c < 12; c++) {
        asm volatile("cp.async.wait_group %0;" :: "n"(NS - 2) : "memory");
        __syncthreads();
        const uint32_t stg = s0 + (c % NS) * STAGEB;
        const uint32_t sAh = stg;
        const uint32_t sAl = stg + TILEB;
        const uint32_t sBh = stg + 2 * TILEB;
        const uint32_t sBl = stg + 3 * TILEB;

        // ldmatrix lane address components
        const int a_row = wm * 32 + (lane & 15);
        const int a_k   = (lane >> 4);               // 0/1 -> k-half unit
        const int b_row = wn * 64 + ((lane & 7) | ((lane >> 4) << 3));
        const int b_k   = ((lane >> 3) & 1);

        #pragma unroll
        for (int ks = 0; ks < 4; ks++) {
            uint32_t ah[2][4], al[2][4], bh[8][2], bl[8][2];
            #pragma unroll
            for (int mt = 0; mt < 2; mt++) {
                uint32_t ad = (uint32_t)((a_row + mt * 16) * ROWB +
                                         (ks * 2 + a_k) * 16);
                ldsm4(ah[mt], sAh + ad);
                ldsm4(al[mt], sAl + ad);
            }
            #pragma unroll
            for (int np = 0; np < 4; np++) {
                uint32_t bd = (uint32_t)((b_row + np * 16) * ROWB +
                                         (ks * 2 + b_k) * 16);
                uint32_t r[4];
                ldsm4(r, sBh + bd);
                bh[np * 2][0] = r[0]; bh[np * 2][1] = r[1];
                bh[np * 2 + 1][0] = r[2]; bh[np * 2 + 1][1] = r[3];
                ldsm4(r, sBl + bd);
                bl[np * 2][0] = r[0]; bl[np * 2][1] = r[1];
                bl[np * 2 + 1][0] = r[2]; bl[np * 2 + 1][1] = r[3];
            }
            #pragma unroll
            for (int mt = 0; mt < 2; mt++)
                #pragma unroll
                for (int nt = 0; nt < 8; nt++) {
                    mma16816(acc[mt][nt], ah[mt], bh[nt]);
                    mma16816(acc[mt][nt], ah[mt], bl[nt]);
                    mma16816(acc[mt][nt], al[mt], bh[nt]);
                }
        }
        __syncthreads();
        if (c + NS < 12) {
            const uint32_t pstg = s0 + (c % NS) * STAGEB;
            const int k0 = (c + NS) * 64;
            #pragma unroll
            for (int p = 0; p < 4; p++) {
                int r = pr + p * 32;
                uint32_t d = pstg + r * ROWB + pu * 16;
                size_t ga = (arow0 + r) * CC + k0 + pu * 8;
                size_t gb = (brow0 + r) * CC + k0 + pu * 8;
                cp16(d,             Ah + ga);
                cp16(d + TILEB,     Al + ga);
                cp16(d + 2 * TILEB, Bh + gb);
                cp16(d + 3 * TILEB, Bl + gb);
            }
        }
        asm volatile("cp.async.commit_group;" ::: "memory");
    }

    // epilogue
    const float* bp = bias + bn * 128;
    #pragma unroll
    for (int mt = 0; mt < 2; mt++) {
        int row0 = bm * 128 + wm * 32 + mt * 16 + (lane >> 2);
        #pragma unroll
        for (int nt = 0; nt < 8; nt++) {
            int col = wn * 64 + nt * 8 + (lane & 3) * 2;
            float b0 = bp[col], b1 = bp[col + 1];
            float2 v0 = make_float2(acc[mt][nt][0] + b0, acc[mt][nt][1] + b1);
            float2 v1 = make_float2(acc[mt][nt][2] + b0, acc[mt][nt][3] + b1);
            *(float2*)(C + (size_t)row0 * CC + bn * 128 + col) = v0;
            *(float2*)(C + (size_t)(row0 + 8) * CC + bn * 128 + col) = v1;
        }
    }
}

// ---------------------------------------------------------------------------
// Axial attention: one CTA per (axis, b, fixed, head). seq=64, d=64.
// Reads fp32 q/k/v; writes bf16 hi/lo attention output for the final GEMM.
// ---------------------------------------------------------------------------
__global__ void __launch_bounds__(256) attn_kernel()
{
    extern __shared__ float smem[];
    float* Qs = smem;                 // [64][64]
    float* Ks = Qs + 64 * 64;         // [64][65] padded
    float* Vs = Ks + 64 * 65;         // [64][64]
    float* Ss = Vs + 64 * 64;         // [64][65] padded

    const int tid = threadIdx.x;
    int idx = blockIdx.x;
    const int axis = idx / (BB * WW * GRP);
    idx -= axis * (BB * WW * GRP);
    const int b     = idx / (WW * GRP);
    int rem         = idx - b * (WW * GRP);
    const int fixed = rem / GRP;
    const int n     = rem - fixed * GRP;

    size_t base;
    int stride;
    if (axis == 0) {
        base   = ((size_t)b * HH * WW + fixed) * CC + n * 64;
        stride = WW * CC;
    } else {
        base   = ((size_t)(b * HH + fixed)) * (size_t)(WW * CC) + (n + GRP) * 64;
        stride = CC;
    }

    for (int t = tid; t < 64 * 64; t += 256) {
        int i = t >> 6, d = t & 63;
        size_t off = base + (size_t)i * stride + d;
        Qs[i * 64 + d] = g_q[off];
        Ks[i * 65 + d] = g_k[off];
        Vs[i * 64 + d] = g_v[off];
    }
    __syncthreads();

    const int tx = tid & 15;
    const int ty = tid >> 4;
    const int i0 = ty * 4;
    const int j0 = tx * 4;

    {
        float acc[4][4];
        #pragma unroll
        for (int a = 0; a < 4; a++)
            #pragma unroll
            for (int c = 0; c < 4; c++) acc[a][c] = 0.0f;
        #pragma unroll 4
        for (int d = 0; d < 64; d++) {
            float qr[4], kr[4];
            #pragma unroll
            for (int a = 0; a < 4; a++) qr[a] = Qs[(i0 + a) * 64 + d];
            #pragma unroll
            for (int c = 0; c < 4; c++) kr[c] = Ks[(j0 + c) * 65 + d];
            #pragma unroll
            for (int a = 0; a < 4; a++)
                #pragma unroll
                for (int c = 0; c < 4; c++)
                    acc[a][c] = fmaf(qr[a], kr[c], acc[a][c]);
        }
        #pragma unroll
        for (int a = 0; a < 4; a++)
            #pragma unroll
            for (int c = 0; c < 4; c++)
                Ss[(i0 + a) * 65 + (j0 + c)] = acc[a][c] * INV_SCALE;
    }
    __syncthreads();

    {
        const int lane = tid & 31;
        const int warp = tid >> 5;
        for (int r = warp * 8; r < warp * 8 + 8; r++) {
            float x0 = Ss[r * 65 + lane];
            float x1 = Ss[r * 65 + lane + 32];
            float m = fmaxf(x0, x1);
            #pragma unroll
            for (int o = 16; o > 0; o >>= 1)
                m = fmaxf(m, __shfl_xor_sync(0xffffffffu, m, o));
            float e0 = __expf(x0 - m);
            float e1 = __expf(x1 - m);
            float s = e0 + e1;
            #pragma unroll
            for (int o = 16; o > 0; o >>= 1)
                s += __shfl_xor_sync(0xffffffffu, s, o);
            float inv = 1.0f / s;
            Ss[r * 65 + lane]      = e0 * inv;
            Ss[r * 65 + lane + 32] = e1 * inv;
        }
    }
    __syncthreads();

    {
        float acc[4][4];
        #pragma unroll
        for (int a = 0; a < 4; a++)
            #pragma unroll
            for (int c = 0; c < 4; c++) acc[a][c] = 0.0f;
        #pragma unroll 4
        for (int j = 0; j < 64; j++) {
            float pr[4], vr[4];
            #pragma unroll
            for (int a = 0; a < 4; a++) pr[a] = Ss[(i0 + a) * 65 + j];
            #pragma unroll
            for (int c = 0; c < 4; c++) vr[c] = Vs[j * 64 + j0 + c];
            #pragma unroll
            for (int a = 0; a < 4; a++)
                #pragma unroll
                for (int c = 0; c < 4; c++)
                    acc[a][c] = fmaf(pr[a], vr[c], acc[a][c]);
        }
        #pragma unroll
        for (int a = 0; a < 4; a++) {
            size_t off = base + (size_t)(i0 + a) * stride + j0;
            __nv_bfloat16 h[4], l[4];
            #pragma unroll
            for (int c = 0; c < 4; c++) {
                h[c] = __float2bfloat16(acc[a][c]);
                l[c] = __float2bfloat16(acc[a][c] - __bfloat162float(h[c]));
            }
            *(uint2*)(g_ah + off) = make_uint2(packbf(h[0], h[1]), packbf(h[2], h[3]));
            *(uint2*)(g_al + off) = make_uint2(packbf(l[0], l[1]), packbf(l[2], l[3]));
        }
    }
}

// ---------------------------------------------------------------------------
extern "C" void kernel_launch(void* const* d_in, const int* in_sizes, int n_in,
                              void* d_out, int out_size)
{
    const float* queries = (const float*)d_in[0];
    const float* values  = (const float*)d_in[1];
    const float* Wq = (const float*)d_in[2];
    const float* bq = (const float*)d_in[3];
    const float* Wk = (const float*)d_in[4];
    const float* bk = (const float*)d_in[5];
    const float* Wv = (const float*)d_in[6];
    const float* bv = (const float*)d_in[7];
    const float* Wo = (const float*)d_in[8];
    const float* bo = (const float*)d_in[9];
    float* out = (float*)d_out;

    float *qp, *kp, *vp;
    __nv_bfloat16 *qh, *ql, *vh, *vl, *ah, *al, *wth, *wtl;
    cudaGetSymbolAddress((void**)&qp, g_q);
    cudaGetSymbolAddress((void**)&kp, g_k);
    cudaGetSymbolAddress((void**)&vp, g_v);
    cudaGetSymbolAddress((void**)&qh, g_qh);
    cudaGetSymbolAddress((void**)&ql, g_ql);
    cudaGetSymbolAddress((void**)&vh, g_vh);
    cudaGetSymbolAddress((void**)&vl, g_vl);
    cudaGetSymbolAddress((void**)&ah, g_ah);
    cudaGetSymbolAddress((void**)&al, g_al);
    cudaGetSymbolAddress((void**)&wth, g_wth);
    cudaGetSymbolAddress((void**)&wtl, g_wtl);

    const int smem_attn = (64 * 64 + 64 * 65 + 64 * 64 + 64 * 65) * 4;
    cudaFuncSetAttribute(attn_kernel, cudaFuncAttributeMaxDynamicSharedMemorySize,
                         smem_attn);
    cudaFuncSetAttribute(gemm_bf16s, cudaFuncAttributeMaxDynamicSharedMemorySize,
                         GEMM_SMEM);

    const int n4 = MTOT * CC / 4;
    const int cblk = (n4 + 255) / 256;

    // input split conversions
    conv_split<<<cblk, 256>>>((const float4*)queries, (uint2*)qh, (uint2*)ql, n4);
    conv_split<<<cblk, 256>>>((const float4*)values,  (uint2*)vh, (uint2*)vl, n4);

    // weight transpose + split
    dim3 wtg(CC / 32, CC / 32), wtb(32, 8);
    wt_split<<<wtg, wtb>>>(Wq, wth + 0 * (size_t)CC * CC, wtl + 0 * (size_t)CC * CC);
    wt_split<<<wtg, wtb>>>(Wk, wth + 1 * (size_t)CC * CC, wtl + 1 * (size_t)CC * CC);
    wt_split<<<wtg, wtb>>>(Wv, wth + 2 * (size_t)CC * CC, wtl + 2 * (size_t)CC * CC);
    wt_split<<<wtg, wtb>>>(Wo, wth + 3 * (size_t)CC * CC, wtl + 3 * (size_t)CC * CC);

    dim3 ggrid(CC / 128, MTOT / 128);   // (6, 512), x fastest -> A-tile L2 reuse
    gemm_bf16s<<<ggrid, 256, GEMM_SMEM>>>(qh, ql, wth + 0 * (size_t)CC * CC,
                                          wtl + 0 * (size_t)CC * CC, bq, qp);
    gemm_bf16s<<<ggrid, 256, GEMM_SMEM>>>(vh, vl, wth + 1 * (size_t)CC * CC,
                                          wtl + 1 * (size_t)CC * CC, bk, kp);
    gemm_bf16s<<<ggrid, 256, GEMM_SMEM>>>(vh, vl, wth + 2 * (size_t)CC * CC,
                                          wtl + 2 * (size_t)CC * CC, bv, vp);

    attn_kernel<<<2 * BB * WW * GRP, 256, smem_attn>>>();

    gemm_bf16s<<<ggrid, 256, GEMM_SMEM>>>(ah, al, wth + 3 * (size_t)CC * CC,
                                          wtl + 3 * (size_t)CC * CC, bo, out);
}

// round 8
// speedup vs baseline: 2.3708x; 1.0676x over previous
#include <cuda_runtime.h>
#include <cuda_bf16.h>
#include <cstdint>

// Problem constants
#define BB   16
#define HH   64
#define WW   64
#define CC   768
#define GRP  6            // heads per axis group
#define MTOT (BB*HH*WW)   // 65536
#define INV_SCALE 0.125f  // 1/sqrt(64)

// ---------------------------------------------------------------------------
// Static device scratch
// ---------------------------------------------------------------------------
__device__ float g_q[MTOT * CC];
__device__ float g_k[MTOT * CC];
__device__ float g_v[MTOT * CC];
__device__ __nv_bfloat16 g_qh[MTOT * CC];
__device__ __nv_bfloat16 g_ql[MTOT * CC];
__device__ __nv_bfloat16 g_vh[MTOT * CC];
__device__ __nv_bfloat16 g_vl[MTOT * CC];
__device__ __nv_bfloat16 g_ah[MTOT * CC];
__device__ __nv_bfloat16 g_al[MTOT * CC];
// transposed split weights: [4][N=768][K=768], order q,k,v,o
__device__ __nv_bfloat16 g_wth[4][CC * CC];
__device__ __nv_bfloat16 g_wtl[4][CC * CC];

// ---------------------------------------------------------------------------
// helpers
// ---------------------------------------------------------------------------
__device__ __forceinline__ uint32_t smem_u32(const void* p) {
    uint32_t a;
    asm("{ .reg .u64 t; cvta.to.shared.u64 t, %1; cvt.u32.u64 %0, t; }"
        : "=r"(a) : "l"(p));
    return a;
}
__device__ __forceinline__ uint32_t packbf(__nv_bfloat16 a, __nv_bfloat16 b) {
    return (uint32_t)__bfloat16_as_ushort(a) |
           ((uint32_t)__bfloat16_as_ushort(b) << 16);
}
__device__ __forceinline__ void cp16(uint32_t dst, const void* src) {
    asm volatile("cp.async.cg.shared.global [%0], [%1], 16;"
                 :: "r"(dst), "l"(src) : "memory");
}
__device__ __forceinline__ void ldsm4(uint32_t* r, uint32_t addr) {
    asm volatile("ldmatrix.sync.aligned.m8n8.x4.shared.b16 {%0,%1,%2,%3}, [%4];"
                 : "=r"(r[0]), "=r"(r[1]), "=r"(r[2]), "=r"(r[3]) : "r"(addr));
}
__device__ __forceinline__ void mma16816(float* d, const uint32_t* a,
                                         const uint32_t* b) {
    asm volatile(
        "mma.sync.aligned.m16n8k16.row.col.f32.bf16.bf16.f32 "
        "{%0,%1,%2,%3}, {%4,%5,%6,%7}, {%8,%9}, {%0,%1,%2,%3};"
        : "+f"(d[0]), "+f"(d[1]), "+f"(d[2]), "+f"(d[3])
        : "r"(a[0]), "r"(a[1]), "r"(a[2]), "r"(a[3]), "r"(b[0]), "r"(b[1]));
}

// ---------------------------------------------------------------------------
// Split conversion: fp32 -> bf16 hi + bf16 lo (4 elems / thread)
// ---------------------------------------------------------------------------
__global__ void conv_split(const float4* __restrict__ x, uint2* __restrict__ h,
                           uint2* __restrict__ l, int n4) {
    int i = blockIdx.x * blockDim.x + threadIdx.x;
    if (i >= n4) return;
    float4 v = x[i];
    __nv_bfloat16 h0 = __float2bfloat16(v.x), h1 = __float2bfloat16(v.y);
    __nv_bfloat16 h2 = __float2bfloat16(v.z), h3 = __float2bfloat16(v.w);
    __nv_bfloat16 l0 = __float2bfloat16(v.x - __bfloat162float(h0));
    __nv_bfloat16 l1 = __float2bfloat16(v.y - __bfloat162float(h1));
    __nv_bfloat16 l2 = __float2bfloat16(v.z - __bfloat162float(h2));
    __nv_bfloat16 l3 = __float2bfloat16(v.w - __bfloat162float(h3));
    h[i] = make_uint2(packbf(h0, h1), packbf(h2, h3));
    l[i] = make_uint2(packbf(l0, l1), packbf(l2, l3));
}

// ---------------------------------------------------------------------------
// Weight transpose + split: W[K=768][N=768] -> Th/Tl [N=768][K=768] bf16
// ---------------------------------------------------------------------------
__global__ void wt_split(const float* __restrict__ W, __nv_bfloat16* __restrict__ Th,
                         __nv_bfloat16* __restrict__ Tl) {
    __shared__ float t[32][33];
    int nb = blockIdx.x * 32, kb = blockIdx.y * 32;
    int tx = threadIdx.x, ty = threadIdx.y;
    #pragma unroll
    for (int j = 0; j < 32; j += 8)
        t[ty + j][tx] = W[(size_t)(kb + ty + j) * CC + nb + tx];
    __syncthreads();
    #pragma unroll
    for (int j = 0; j < 32; j += 8) {
        float v = t[tx][ty + j];   // = W[kb+tx][nb+ty+j]
        __nv_bfloat16 h = __float2bfloat16(v);
        __nv_bfloat16 l = __float2bfloat16(v - __bfloat162float(h));
        size_t o = (size_t)(nb + ty + j) * CC + kb + tx;
        Th[o] = h;
        Tl[o] = l;
    }
}

// ---------------------------------------------------------------------------
// mma.sync bf16 split GEMM: C[M,N] = (Ah+Al)[M,K]*(Bh+Bl)^T[N,K] + bias[N]
// CTA tile 128x128, BK=64 elems (128B rows), 3-stage cp.async.
// 256 threads (8 warps, 4Mx2N). rows padded to 144B -> ldmatrix conflict-free.
// Dual-output: grid.x in [0,2*NBX): x>=NBX selects the second (B,bias,C) set,
// so two GEMMs sharing the same A run in one launch (A-tile L2 reuse).
// ---------------------------------------------------------------------------
#define NS       3
#define ROWB     144                    // padded row stride in bytes (128 data)
#define TILEB    (128 * ROWB)           // 18432 B per tile
#define STAGEB   (4 * TILEB)            // Ah, Al, Bh, Bl = 73728 B
#define GEMM_SMEM (NS * STAGEB)         // 221184 B
#define NBX      (CC / 128)             // 6 N-tiles per output

__global__ void __launch_bounds__(256, 1) gemm_bf16s(
    const __nv_bfloat16* __restrict__ Ah, const __nv_bfloat16* __restrict__ Al,
    const __nv_bfloat16* __restrict__ Bh0, const __nv_bfloat16* __restrict__ Bl0,
    const float* __restrict__ bias0, float* __restrict__ C0,
    const __nv_bfloat16* __restrict__ Bh1, const __nv_bfloat16* __restrict__ Bl1,
    const float* __restrict__ bias1, float* __restrict__ C1)
{
    extern __shared__ char sm_raw[];
    const uint32_t s0 = smem_u32(sm_raw);

    const int tid  = threadIdx.x;
    const int lane = tid & 31;
    const int wid  = tid >> 5;
    const int wm   = wid >> 1;          // 0..3 -> M offset wm*32
    const int wn   = wid & 1;           // 0..1 -> N offset wn*64

    const int bnx = blockIdx.x;
    const bool second = bnx >= NBX;
    const int bn = second ? bnx - NBX : bnx;
    const int bm = blockIdx.y;
    const __nv_bfloat16* __restrict__ Bh = second ? Bh1 : Bh0;
    const __nv_bfloat16* __restrict__ Bl = second ? Bl1 : Bl0;
    const float* __restrict__ bias = second ? bias1 : bias0;
    float* __restrict__ C = second ? C1 : C0;

    const size_t arow0 = (size_t)bm * 128;
    const size_t brow0 = (size_t)bn * 128;

    // producer mapping: pu = 16B unit within 128B row (0..7), pr = row (0..31)
    const int pu = tid & 7;
    const int pr = tid >> 3;

    float acc[2][8][4];
    #pragma unroll
    for (int mt = 0; mt < 2; mt++)
        #pragma unroll
        for (int nt = 0; nt < 8; nt++)
            #pragma unroll
            for (int e = 0; e < 4; e++) acc[mt][nt][e] = 0.0f;

    // --- prefetch first NS chunks ---
    #pragma unroll
    for (int c = 0; c < NS; c++) {
        const uint32_t stg = s0 + c * STAGEB;
        const int k0 = c * 64;
        #pragma unroll
        for (int p = 0; p < 4; p++) {
            int r = pr + p * 32;
            uint32_t d = stg + r * ROWB + pu * 16;
            size_t ga = (arow0 + r) * CC + k0 + pu * 8;
            size_t gb = (brow0 + r) * CC + k0 + pu * 8;
            cp16(d,              Ah + ga);
            cp16(d + TILEB,      Al + ga);
            cp16(d + 2 * TILEB,  Bh + gb);
            cp16(d + 3 * TILEB,  Bl + gb);
        }
        asm volatile("cp.async.commit_group;" ::: "memory");
    }

    for (int c = 0; c < 12; c++) {
        asm volatile("cp.async.wait_group %0;" :: "n"(NS - 2) : "memory");
        __syncthreads();
        const uint32_t stg = s0 + (c % NS) * STAGEB;
        const uint32_t sAh = stg;
        const uint32_t sAl = stg + TILEB;
        const uint32_t sBh = stg + 2 * TILEB;
        const uint32_t sBl = stg + 3 * TILEB;

        // ldmatrix lane address components
        const int a_row = wm * 32 + (lane & 15);
        const int a_k   = (lane >> 4);               // 0/1 -> k-half unit
        const int b_row = wn * 64 + ((lane & 7) | ((lane >> 4) << 3));
        const int b_k   = ((lane >> 3) & 1);

        #pragma unroll
        for (int ks = 0; ks < 4; ks++) {
            uint32_t ah[2][4], al[2][4], bh[8][2], bl[8][2];
            #pragma unroll
            for (int mt = 0; mt < 2; mt++) {
                uint32_t ad = (uint32_t)((a_row + mt * 16) * ROWB +
                                         (ks * 2 + a_k) * 16);
                ldsm4(ah[mt], sAh + ad);
                ldsm4(al[mt], sAl + ad);
            }
            #pragma unroll
            for (int np = 0; np < 4; np++) {
                uint32_t bd = (uint32_t)((b_row + np * 16) * ROWB +
                                         (ks * 2 + b_k) * 16);
                uint32_t r[4];
                ldsm4(r, sBh + bd);
                bh[np * 2][0] = r[0]; bh[np * 2][1] = r[1];
                bh[np * 2 + 1][0] = r[2]; bh[np * 2 + 1][1] = r[3];
                ldsm4(r, sBl + bd);
                bl[np * 2][0] = r[0]; bl[np * 2][1] = r[1];
                bl[np * 2 + 1][0] = r[2]; bl[np * 2 + 1][1] = r[3];
            }
            #pragma unroll
            for (int mt = 0; mt < 2; mt++)
                #pragma unroll
                for (int nt = 0; nt < 8; nt++) {
                    mma16816(acc[mt][nt], ah[mt], bh[nt]);
                    mma16816(acc[mt][nt], ah[mt], bl[nt]);
                    mma16816(acc[mt][nt], al[mt], bh[nt]);
                }
        }
        __syncthreads();
        if (c + NS < 12) {
            const uint32_t pstg = s0 + (c % NS) * STAGEB;
            const int k0 = (c + NS) * 64;
            #pragma unroll
            for (int p = 0; p < 4; p++) {
                int r = pr + p * 32;
                uint32_t d = pstg + r * ROWB + pu * 16;
                size_t ga = (arow0 + r) * CC + k0 + pu * 8;
                size_t gb = (brow0 + r) * CC + k0 + pu * 8;
                cp16(d,             Ah + ga);
                cp16(d + TILEB,     Al + ga);
                cp16(d + 2 * TILEB, Bh + gb);
                cp16(d + 3 * TILEB, Bl + gb);
            }
        }
        asm volatile("cp.async.commit_group;" ::: "memory");
    }

    // epilogue
    const float* bp = bias + bn * 128;
    #pragma unroll
    for (int mt = 0; mt < 2; mt++) {
        int row0 = bm * 128 + wm * 32 + mt * 16 + (lane >> 2);
        #pragma unroll
        for (int nt = 0; nt < 8; nt++) {
            int col = wn * 64 + nt * 8 + (lane & 3) * 2;
            float b0 = bp[col], b1 = bp[col + 1];
            float2 v0 = make_float2(acc[mt][nt][0] + b0, acc[mt][nt][1] + b1);
            float2 v1 = make_float2(acc[mt][nt][2] + b0, acc[mt][nt][3] + b1);
            *(float2*)(C + (size_t)row0 * CC + bn * 128 + col) = v0;
            *(float2*)(C + (size_t)(row0 + 8) * CC + bn * 128 + col) = v1;
        }
    }
}

// ---------------------------------------------------------------------------
// Axial attention: one CTA per (axis, b, fixed, head). seq=64, d=64.
// Register softmax (16-lane shfl groups); P reuses the Q smem buffer
// -> smem 49.4KB -> 4 CTAs/SM. float4 global loads.
// ---------------------------------------------------------------------------
#define ATTN_SMEM ((4096 + 4160 + 4096) * 4)   // Qs/P, Ks(65-pad), Vs

__global__ void __launch_bounds__(256) attn_kernel()
{
    extern __shared__ float smem[];
    float* Qs = smem;                 // [64][64], reused for P
    float* Ks = Qs + 4096;            // [64][65] padded
    float* Vs = Ks + 4160;            // [64][64]

    const int tid = threadIdx.x;
    int idx = blockIdx.x;
    const int axis = idx / (BB * WW * GRP);
    idx -= axis * (BB * WW * GRP);
    const int b     = idx / (WW * GRP);
    int rem         = idx - b * (WW * GRP);
    const int fixed = rem / GRP;
    const int n     = rem - fixed * GRP;

    size_t base;
    int stride;
    if (axis == 0) {
        base   = ((size_t)b * HH * WW + fixed) * CC + n * 64;
        stride = WW * CC;
    } else {
        base   = ((size_t)(b * HH + fixed)) * (size_t)(WW * CC) + (n + GRP) * 64;
        stride = CC;
    }

    // float4 loads: 1024 units of 16B
    for (int t = tid; t < 1024; t += 256) {
        int i = t >> 4, d = (t & 15) * 4;
        size_t off = base + (size_t)i * stride + d;
        float4 q4 = *(const float4*)(g_q + off);
        float4 k4 = *(const float4*)(g_k + off);
        float4 v4 = *(const float4*)(g_v + off);
        *(float4*)(Qs + i * 64 + d) = q4;
        Ks[i * 65 + d + 0] = k4.x; Ks[i * 65 + d + 1] = k4.y;
        Ks[i * 65 + d + 2] = k4.z; Ks[i * 65 + d + 3] = k4.w;
        *(float4*)(Vs + i * 64 + d) = v4;
    }
    __syncthreads();

    const int tx = tid & 15;
    const int ty = tid >> 4;
    const int i0 = ty * 4;
    const int j0 = tx * 4;

    // S tile in registers
    float acc[4][4];
    #pragma unroll
    for (int a = 0; a < 4; a++)
        #pragma unroll
        for (int c = 0; c < 4; c++) acc[a][c] = 0.0f;
    #pragma unroll 4
    for (int d = 0; d < 64; d++) {
        float qr[4], kr[4];
        #pragma unroll
        for (int a = 0; a < 4; a++) qr[a] = Qs[(i0 + a) * 64 + d];
        #pragma unroll
        for (int c = 0; c < 4; c++) kr[c] = Ks[(j0 + c) * 65 + d];
        #pragma unroll
        for (int a = 0; a < 4; a++)
            #pragma unroll
            for (int c = 0; c < 4; c++)
                acc[a][c] = fmaf(qr[a], kr[c], acc[a][c]);
    }

    // register softmax per row: threads sharing a row (same ty) are a
    // contiguous 16-lane group -> shfl_xor 1/2/4/8 stays in-group.
    #pragma unroll
    for (int a = 0; a < 4; a++) {
        float m = fmaxf(fmaxf(acc[a][0], acc[a][1]), fmaxf(acc[a][2], acc[a][3]));
        #pragma unroll
        for (int o = 8; o > 0; o >>= 1)
            m = fmaxf(m, __shfl_xor_sync(0xffffffffu, m, o));
        float e0 = __expf((acc[a][0] - m) * INV_SCALE);
        float e1 = __expf((acc[a][1] - m) * INV_SCALE);
        float e2 = __expf((acc[a][2] - m) * INV_SCALE);
        float e3 = __expf((acc[a][3] - m) * INV_SCALE);
        float s = e0 + e1 + e2 + e3;
        #pragma unroll
        for (int o = 8; o > 0; o >>= 1)
            s += __shfl_xor_sync(0xffffffffu, s, o);
        float inv = 1.0f / s;
        acc[a][0] = e0 * inv; acc[a][1] = e1 * inv;
        acc[a][2] = e2 * inv; acc[a][3] = e3 * inv;
    }

    __syncthreads();   // all Qs/Ks reads done -> safe to overwrite Qs with P
    #pragma unroll
    for (int a = 0; a < 4; a++)
        *(float4*)(Qs + (i0 + a) * 64 + j0) =
            make_float4(acc[a][0], acc[a][1], acc[a][2], acc[a][3]);
    __syncthreads();

    // O = P V
    {
        float o_[4][4];
        #pragma unroll
        for (int a = 0; a < 4; a++)
            #pragma unroll
            for (int c = 0; c < 4; c++) o_[a][c] = 0.0f;
        #pragma unroll 4
        for (int j = 0; j < 64; j++) {
            float pr[4], vr[4];
            #pragma unroll
            for (int a = 0; a < 4; a++) pr[a] = Qs[(i0 + a) * 64 + j];
            #pragma unroll
            for (int c = 0; c < 4; c++) vr[c] = Vs[j * 64 + j0 + c];
            #pragma unroll
            for (int a = 0; a < 4; a++)
                #pragma unroll
                for (int c = 0; c < 4; c++)
                    o_[a][c] = fmaf(pr[a], vr[c], o_[a][c]);
        }
        #pragma unroll
        for (int a = 0; a < 4; a++) {
            size_t off = base + (size_t)(i0 + a) * stride + j0;
            __nv_bfloat16 h[4], l[4];
            #pragma unroll
            for (int c = 0; c < 4; c++) {
                h[c] = __float2bfloat16(o_[a][c]);
                l[c] = __float2bfloat16(o_[a][c] - __bfloat162float(h[c]));
            }
            *(uint2*)(g_ah + off) = make_uint2(packbf(h[0], h[1]), packbf(h[2], h[3]));
            *(uint2*)(g_al + off) = make_uint2(packbf(l[0], l[1]), packbf(l[2], l[3]));
        }
    }
}

// ---------------------------------------------------------------------------
extern "C" void kernel_launch(void* const* d_in, const int* in_sizes, int n_in,
                              void* d_out, int out_size)
{
    const float* queries = (const float*)d_in[0];
    const float* values  = (const float*)d_in[1];
    const float* Wq = (const float*)d_in[2];
    const float* bq = (const float*)d_in[3];
    const float* Wk = (const float*)d_in[4];
    const float* bk = (const float*)d_in[5];
    const float* Wv = (const float*)d_in[6];
    const float* bv = (const float*)d_in[7];
    const float* Wo = (const float*)d_in[8];
    const float* bo = (const float*)d_in[9];
    float* out = (float*)d_out;

    float *qp, *kp, *vp;
    __nv_bfloat16 *qh, *ql, *vh, *vl, *ah, *al, *wth, *wtl;
    cudaGetSymbolAddress((void**)&qp, g_q);
    cudaGetSymbolAddress((void**)&kp, g_k);
    cudaGetSymbolAddress((void**)&vp, g_v);
    cudaGetSymbolAddress((void**)&qh, g_qh);
    cudaGetSymbolAddress((void**)&ql, g_ql);
    cudaGetSymbolAddress((void**)&vh, g_vh);
    cudaGetSymbolAddress((void**)&vl, g_vl);
    cudaGetSymbolAddress((void**)&ah, g_ah);
    cudaGetSymbolAddress((void**)&al, g_al);
    cudaGetSymbolAddress((void**)&wth, g_wth);
    cudaGetSymbolAddress((void**)&wtl, g_wtl);

    cudaFuncSetAttribute(attn_kernel, cudaFuncAttributeMaxDynamicSharedMemorySize,
                         ATTN_SMEM);
    cudaFuncSetAttribute(gemm_bf16s, cudaFuncAttributeMaxDynamicSharedMemorySize,
                         GEMM_SMEM);

    const int n4 = MTOT * CC / 4;
    const int cblk = (n4 + 255) / 256;

    // input split conversions
    conv_split<<<cblk, 256>>>((const float4*)queries, (uint2*)qh, (uint2*)ql, n4);
    conv_split<<<cblk, 256>>>((const float4*)values,  (uint2*)vh, (uint2*)vl, n4);

    // weight transpose + split
    dim3 wtg(CC / 32, CC / 32), wtb(32, 8);
    __nv_bfloat16* WqH = wth + 0 * (size_t)CC * CC; __nv_bfloat16* WqL = wtl + 0 * (size_t)CC * CC;
    __nv_bfloat16* WkH = wth + 1 * (size_t)CC * CC; __nv_bfloat16* WkL = wtl + 1 * (size_t)CC * CC;
    __nv_bfloat16* WvH = wth + 2 * (size_t)CC * CC; __nv_bfloat16* WvL = wtl + 2 * (size_t)CC * CC;
    __nv_bfloat16* WoH = wth + 3 * (size_t)CC * CC; __nv_bfloat16* WoL = wtl + 3 * (size_t)CC * CC;
    wt_split<<<wtg, wtb>>>(Wq, WqH, WqL);
    wt_split<<<wtg, wtb>>>(Wk, WkH, WkL);
    wt_split<<<wtg, wtb>>>(Wv, WvH, WvL);
    wt_split<<<wtg, wtb>>>(Wo, WoH, WoL);

    // Q projection (single output)
    dim3 g1(NBX, MTOT / 128);
    gemm_bf16s<<<g1, 256, GEMM_SMEM>>>(qh, ql, WqH, WqL, bq, qp,
                                       WqH, WqL, bq, qp);
    // K and V projections fused (shared A = values)
    dim3 g2(2 * NBX, MTOT / 128);
    gemm_bf16s<<<g2, 256, GEMM_SMEM>>>(vh, vl, WkH, WkL, bk, kp,
                                       WvH, WvL, bv, vp);

    attn_kernel<<<2 * BB * WW * GRP, 256, ATTN_SMEM>>>();

    // output projection
    gemm_bf16s<<<g1, 256, GEMM_SMEM>>>(ah, al, WoH, WoL, bo, out,
                                       WoH, WoL, bo, out);
}